// round 14
// baseline (speedup 1.0000x reference)
#include <cuda_runtime.h>
#include <cuda_fp16.h>
#include <math.h>
#include <stdint.h>

// StableMoEGate v9: fp16 m16n8k16, 2-way split (3 passes), A AND B staged via
// cp.async double-buffered smem (no in-loop LDG). 2 K-groups x 4 token-quarters.
// logits = x @ W^T (T=16384, H=4096, E=64); softmax; top-2; renorm softmax.
// Output: single f32 buffer [2T scores][2T idx-as-float][1 aux=0].

#define Hdim 4096
#define Edim 64
#define MT   64
#define NCHUNK 64               // chunks per K-group (2048 k / 32)
#define A_STRIDE 144            // padded A row bytes (32 floats + 16B pad)
#define A_BYTES  18432          // 128 rows (2g x 64 tok) * 144
#define B_BYTES  16384          // 2g x 2s x 2spl x 64n x 32B
#define BUFB     (A_BYTES + B_BYTES)   // 34816
#define SMEM_BYTES (2 * BUFB)          // 69632

// W pre-split to fp16 hi/lo: [spl][kstep:256][n:64][quad:4][half16:2][bit:2]
__device__ __half g_wsplit[2 * 64 * 4096];

static __device__ __forceinline__ uint32_t smem_u32(const void* p) {
    uint32_t a;
    asm("{ .reg .u64 t; cvta.to.shared.u64 t, %1; cvt.u32.u64 %0, t; }" : "=r"(a) : "l"(p));
    return a;
}
static __device__ __forceinline__ uint32_t h2u(__half2 h) {
    return *reinterpret_cast<uint32_t*>(&h);
}

__global__ void __launch_bounds__(256) split_w_kernel(const float* __restrict__ W) {
    const int i = blockIdx.x * 256 + threadIdx.x;
    if (i < 64 * 4096) {
        const int n = i >> 12, k = i & 4095;
        const float w = W[(size_t)n * 4096 + k];
        const __half hi = __float2half_rn(w);
        const __half lo = __float2half_rn(w - __half2float(hi));
        const int kin = k & 15;
        const int half = kin >> 3, quad = (kin & 7) >> 1, bit = kin & 1;
        const int idx = ((k >> 4) * 64 + n) * 16 + quad * 4 + half * 2 + bit;
        g_wsplit[idx]          = hi;
        g_wsplit[262144 + idx] = lo;
    }
}

#define MMAH(d, a0, a1, a2, a3, b0, b1)                                          \
    asm("mma.sync.aligned.m16n8k16.row.col.f32.f16.f16.f32 "                     \
        "{%0,%1,%2,%3}, {%4,%5,%6,%7}, {%8,%9}, {%0,%1,%2,%3};"                  \
        : "+f"(d[0]), "+f"(d[1]), "+f"(d[2]), "+f"(d[3])                         \
        : "r"(a0), "r"(a1), "r"(a2), "r"(a3), "r"(b0), "r"(b1))

__global__ void __launch_bounds__(256, 2) moe_gate_v9_kernel(
    const float* __restrict__ x,
    float* __restrict__ out,
    int T)
{
    extern __shared__ float smem[];
    const uint32_t sbase = smem_u32(smem);

    const int tid  = threadIdx.x;
    const int lid  = tid & 31;
    const int wid  = tid >> 5;
    const int g    = wid >> 2;            // K-group 0..1 : k in [g*2048, +2048)
    const int tq   = wid & 3;             // token quarter: rows tq*16..tq*16+15
    const int gid  = lid >> 2;            // 0..7
    const int tid4 = lid & 3;             // 0..3
    const int m0   = blockIdx.x * MT;

    // ---- cp.async loader constants ----
    // A: 4 x 16B per thread: j -> (gA = j>>1, tokA = (j&1)*32 + tid>>3), q = tid&7
    const int qA   = tid & 7;
    const int tokL = tid >> 3;            // 0..31
    // B: 4 x 16B per thread: j -> (gB = j>>1, sB = j&1); tid -> spl,n,hf
    const int splL = (tid >> 7) & 1;
    const int nL   = (tid >> 1) & 63;
    const int hfL  = tid & 1;
    const char* wbase = (const char*)g_wsplit;
    const char* xbase = (const char*)x;

    auto issue = [&](int c) {
        const uint32_t base = sbase + (uint32_t)(c & 1) * BUFB;
        #pragma unroll
        for (int j = 0; j < 4; j++) {                 // A
            const int gA = j >> 1, tokA = (j & 1) * 32 + tokL;
            const uint32_t dst = base + (uint32_t)((gA * 64 + tokA) * A_STRIDE + qA * 16);
            const char* src = xbase
                + ((size_t)(m0 + tokA) * Hdim + (size_t)gA * 2048 + (size_t)c * 32) * 4
                + qA * 16;
            asm volatile("cp.async.cg.shared.global [%0], [%1], 16;" :: "r"(dst), "l"(src));
        }
        #pragma unroll
        for (int j = 0; j < 4; j++) {                 // B
            const int gB = j >> 1, sB = j & 1;
            const uint32_t dst = base + (uint32_t)A_BYTES
                + (uint32_t)((((gB * 2 + sB) * 2 + splL) * 64 + nL) * 32 + hfL * 16);
            const char* src = wbase + (size_t)splL * 524288
                + ((size_t)((gB * 128 + c * 2 + sB) * 64 + nL) * 32 + hfL * 16);
            asm volatile("cp.async.cg.shared.global [%0], [%1], 16;" :: "r"(dst), "l"(src));
        }
        asm volatile("cp.async.commit_group;" ::: "memory");
    };

    float acc[8][4];
    #pragma unroll
    for (int nt = 0; nt < 8; nt++)
        #pragma unroll
        for (int q = 0; q < 4; q++) acc[nt][q] = 0.0f;

    // A read addresses (within buffer, step s adds 64B): rows tq*16+gid, +8
    const uint32_t arow0 = (uint32_t)((g * 64 + tq * 16 + gid) * A_STRIDE + tid4 * 8);
    const uint32_t arow1 = arow0 + 8u * A_STRIDE;

    issue(0);

    for (int c = 0; c < NCHUNK; c++) {
        asm volatile("cp.async.wait_group 0;" ::: "memory");
        __syncthreads();
        if (c + 1 < NCHUNK) issue(c + 1);

        const uint32_t base = sbase + (uint32_t)(c & 1) * BUFB;
        #pragma unroll
        for (int s = 0; s < 2; s++) {
            // A fragments from smem: a0=(r,2t..),a1=(r+8),a2=(r,+8k),a3=(r+8,+8k)
            float2 v0, v1, v2, v3;
            const uint32_t sa = (uint32_t)(s * 64);
            asm volatile("ld.shared.v2.f32 {%0,%1},[%2];" : "=f"(v0.x), "=f"(v0.y) : "r"(base + arow0 + sa));
            asm volatile("ld.shared.v2.f32 {%0,%1},[%2];" : "=f"(v1.x), "=f"(v1.y) : "r"(base + arow1 + sa));
            asm volatile("ld.shared.v2.f32 {%0,%1},[%2];" : "=f"(v2.x), "=f"(v2.y) : "r"(base + arow0 + sa + 32u));
            asm volatile("ld.shared.v2.f32 {%0,%1},[%2];" : "=f"(v3.x), "=f"(v3.y) : "r"(base + arow1 + sa + 32u));

            uint32_t ahi[4], alo[4];
            {
                const float2 vv[4] = {v0, v1, v2, v3};
                #pragma unroll
                for (int i = 0; i < 4; i++) {
                    const __half2 h = __float22half2_rn(vv[i]);
                    const float2 f = __half22float2(h);
                    ahi[i] = h2u(h);
                    alo[i] = h2u(__floats2half2_rn(vv[i].x - f.x, vv[i].y - f.y));
                }
            }

            const uint32_t b0a = base + (uint32_t)A_BYTES
                               + (uint32_t)(((g * 2 + s) * 2) * 2048)
                               + (uint32_t)(gid * 32 + tid4 * 8);
            #pragma unroll
            for (int nt = 0; nt < 8; nt++) {
                uint32_t bh0, bh1, bl0, bl1;
                asm volatile("ld.shared.v2.b32 {%0,%1},[%2];"
                             : "=r"(bh0), "=r"(bh1) : "r"(b0a + (uint32_t)(nt * 256)));
                asm volatile("ld.shared.v2.b32 {%0,%1},[%2];"
                             : "=r"(bl0), "=r"(bl1) : "r"(b0a + (uint32_t)(nt * 256) + 2048u));
                MMAH(acc[nt], ahi[0], ahi[1], ahi[2], ahi[3], bh0, bh1);
                MMAH(acc[nt], ahi[0], ahi[1], ahi[2], ahi[3], bl0, bl1);
                MMAH(acc[nt], alo[0], alo[1], alo[2], alo[3], bh0, bh1);
            }
        }
    }
    __syncthreads();

    // ---- split-K(2) reduction into logits smem [64][68] ----
    #pragma unroll
    for (int gg = 0; gg < 2; gg++) {
        if (g == gg) {
            const int r = tq * 16 + gid;
            #pragma unroll
            for (int nt = 0; nt < 8; nt++) {
                const int col = nt * 8 + tid4 * 2;
                if (gg == 0) {
                    smem[r * 68 + col]           = acc[nt][0];
                    smem[r * 68 + col + 1]       = acc[nt][1];
                    smem[(r + 8) * 68 + col]     = acc[nt][2];
                    smem[(r + 8) * 68 + col + 1] = acc[nt][3];
                } else {
                    smem[r * 68 + col]           += acc[nt][0];
                    smem[r * 68 + col + 1]       += acc[nt][1];
                    smem[(r + 8) * 68 + col]     += acc[nt][2];
                    smem[(r + 8) * 68 + col + 1] += acc[nt][3];
                }
            }
        }
        __syncthreads();
    }

    if (tid < MT) {
        const float* row = smem + tid * 68;
        float best1 = -3.4e38f, best2 = -3.4e38f;
        int i1 = 0, i2 = 0;
        #pragma unroll 8
        for (int e = 0; e < Edim; e++) {
            const float l = row[e];
            if (l > best1) { best2 = best1; i2 = i1; best1 = l; i1 = e; }
            else if (l > best2) { best2 = l; i2 = e; }
        }
        float Z = 0.0f;
        #pragma unroll 8
        for (int e = 0; e < Edim; e++) Z += expf(row[e] - best1);
        const float s1 = 1.0f / Z;
        const float s2 = expf(best2 - best1) / Z;
        const float p1 = 1.0f / (1.0f + expf(s2 - s1));
        const float p2 = 1.0f - p1;

        const int m = m0 + tid;
        out[2 * m + 0] = p1;
        out[2 * m + 1] = p2;
        float* oi = out + 2 * T;              // indices stored as float values
        oi[2 * m + 0] = (float)i1;
        oi[2 * m + 1] = (float)i2;
    }
    if (blockIdx.x == 0 && tid == 0) out[4 * T] = 0.0f;
}

extern "C" void kernel_launch(void* const* d_in, const int* in_sizes, int n_in,
                              void* d_out, int out_size)
{
    const float* x = (const float*)d_in[0];
    const float* W = (const float*)d_in[1];
    int T = in_sizes[0] / Hdim;   // 16384
    (void)n_in; (void)out_size;

    static bool attr_done = false;
    if (!attr_done) {
        cudaFuncSetAttribute(moe_gate_v9_kernel,
                             cudaFuncAttributeMaxDynamicSharedMemorySize, SMEM_BYTES);
        attr_done = true;
    }
    split_w_kernel<<<1024, 256>>>(W);
    moe_gate_v9_kernel<<<T / MT, 256, SMEM_BYTES>>>(x, (float*)d_out, T);
}

// round 15
// speedup vs baseline: 1.0541x; 1.0541x over previous
#include <cuda_runtime.h>
#include <cuda_fp16.h>
#include <math.h>
#include <stdint.h>

// StableMoEGate v10: fp16 m16n8k16, 2-way split (3 passes), A+B via cp.async
// with a THREE-stage pipeline (wait_group 1; chunk c+2 in flight) to cover
// DRAM latency. 2 K-groups x 4 token-quarters, 256 thr, 2 CTA/SM.
// logits = x @ W^T (T=16384, H=4096, E=64); softmax; top-2; renorm softmax.
// Output: single f32 buffer [2T scores][2T idx-as-float][1 aux=0].

#define Hdim 4096
#define Edim 64
#define MT   64
#define NCHUNK 64               // chunks per K-group (2048 k / 32)
#define A_STRIDE 144            // padded A row bytes (32 floats + 16B pad)
#define A_BYTES  18432          // 128 rows (2g x 64 tok) * 144
#define B_BYTES  16384          // 2g x 2s x 2spl x 64n x 32B
#define BUFB     (A_BYTES + B_BYTES)   // 34816
#define NSTAGE   3
#define SMEM_BYTES (NSTAGE * BUFB)     // 104448

// W pre-split to fp16 hi/lo: [spl][kstep:256][n:64][quad:4][half16:2][bit:2]
__device__ __half g_wsplit[2 * 64 * 4096];

static __device__ __forceinline__ uint32_t smem_u32(const void* p) {
    uint32_t a;
    asm("{ .reg .u64 t; cvta.to.shared.u64 t, %1; cvt.u32.u64 %0, t; }" : "=r"(a) : "l"(p));
    return a;
}
static __device__ __forceinline__ uint32_t h2u(__half2 h) {
    return *reinterpret_cast<uint32_t*>(&h);
}

__global__ void __launch_bounds__(256) split_w_kernel(const float* __restrict__ W) {
    const int i = blockIdx.x * 256 + threadIdx.x;
    if (i < 64 * 4096) {
        const int n = i >> 12, k = i & 4095;
        const float w = W[(size_t)n * 4096 + k];
        const __half hi = __float2half_rn(w);
        const __half lo = __float2half_rn(w - __half2float(hi));
        const int kin = k & 15;
        const int half = kin >> 3, quad = (kin & 7) >> 1, bit = kin & 1;
        const int idx = ((k >> 4) * 64 + n) * 16 + quad * 4 + half * 2 + bit;
        g_wsplit[idx]          = hi;
        g_wsplit[262144 + idx] = lo;
    }
}

#define MMAH(d, a0, a1, a2, a3, b0, b1)                                          \
    asm("mma.sync.aligned.m16n8k16.row.col.f32.f16.f16.f32 "                     \
        "{%0,%1,%2,%3}, {%4,%5,%6,%7}, {%8,%9}, {%0,%1,%2,%3};"                  \
        : "+f"(d[0]), "+f"(d[1]), "+f"(d[2]), "+f"(d[3])                         \
        : "r"(a0), "r"(a1), "r"(a2), "r"(a3), "r"(b0), "r"(b1))

__global__ void __launch_bounds__(256, 2) moe_gate_v10_kernel(
    const float* __restrict__ x,
    float* __restrict__ out,
    int T)
{
    extern __shared__ float smem[];
    const uint32_t sbase = smem_u32(smem);

    const int tid  = threadIdx.x;
    const int lid  = tid & 31;
    const int wid  = tid >> 5;
    const int g    = wid >> 2;            // K-group 0..1 : k in [g*2048, +2048)
    const int tq   = wid & 3;             // token quarter: rows tq*16..tq*16+15
    const int gid  = lid >> 2;            // 0..7
    const int tid4 = lid & 3;             // 0..3
    const int m0   = blockIdx.x * MT;

    // ---- cp.async loader constants ----
    const int qA   = tid & 7;
    const int tokL = tid >> 3;            // 0..31
    const int splL = (tid >> 7) & 1;
    const int nL   = (tid >> 1) & 63;
    const int hfL  = tid & 1;
    const char* wbase = (const char*)g_wsplit;
    const char* xbase = (const char*)x;

    auto issue = [&](int c, int buf) {
        const uint32_t base = sbase + (uint32_t)buf * BUFB;
        #pragma unroll
        for (int j = 0; j < 4; j++) {                 // A
            const int gA = j >> 1, tokA = (j & 1) * 32 + tokL;
            const uint32_t dst = base + (uint32_t)((gA * 64 + tokA) * A_STRIDE + qA * 16);
            const char* src = xbase
                + ((size_t)(m0 + tokA) * Hdim + (size_t)gA * 2048 + (size_t)c * 32) * 4
                + qA * 16;
            asm volatile("cp.async.cg.shared.global [%0], [%1], 16;" :: "r"(dst), "l"(src));
        }
        #pragma unroll
        for (int j = 0; j < 4; j++) {                 // B
            const int gB = j >> 1, sB = j & 1;
            const uint32_t dst = base + (uint32_t)A_BYTES
                + (uint32_t)((((gB * 2 + sB) * 2 + splL) * 64 + nL) * 32 + hfL * 16);
            const char* src = wbase + (size_t)splL * 524288
                + ((size_t)((gB * 128 + c * 2 + sB) * 64 + nL) * 32 + hfL * 16);
            asm volatile("cp.async.cg.shared.global [%0], [%1], 16;" :: "r"(dst), "l"(src));
        }
        asm volatile("cp.async.commit_group;" ::: "memory");
    };

    float acc[8][4];
    #pragma unroll
    for (int nt = 0; nt < 8; nt++)
        #pragma unroll
        for (int q = 0; q < 4; q++) acc[nt][q] = 0.0f;

    const uint32_t arow0 = (uint32_t)((g * 64 + tq * 16 + gid) * A_STRIDE + tid4 * 8);
    const uint32_t arow1 = arow0 + 8u * A_STRIDE;

    // 3-stage prologue
    issue(0, 0);
    issue(1, 1);

    int bufc = 0;                          // buffer holding chunk c
    for (int c = 0; c < NCHUNK; c++) {
        // chunk c guaranteed complete; chunk c+1 may still be in flight
        asm volatile("cp.async.wait_group 1;" ::: "memory");
        __syncthreads();

        // issue chunk c+2 into the buffer freed by chunk c-1 (all warps done
        // with it: they passed the barrier above). Empty commit at the tail
        // keeps group counts aligned so wait_group 1 stays correct.
        if (c + 2 < NCHUNK) {
            int bufn = bufc + 2; if (bufn >= NSTAGE) bufn -= NSTAGE;
            issue(c + 2, bufn);
        } else {
            asm volatile("cp.async.commit_group;" ::: "memory");
        }

        const uint32_t base = sbase + (uint32_t)bufc * BUFB;
        #pragma unroll
        for (int s = 0; s < 2; s++) {
            float2 v0, v1, v2, v3;
            const uint32_t sa = (uint32_t)(s * 64);
            asm volatile("ld.shared.v2.f32 {%0,%1},[%2];" : "=f"(v0.x), "=f"(v0.y) : "r"(base + arow0 + sa));
            asm volatile("ld.shared.v2.f32 {%0,%1},[%2];" : "=f"(v1.x), "=f"(v1.y) : "r"(base + arow1 + sa));
            asm volatile("ld.shared.v2.f32 {%0,%1},[%2];" : "=f"(v2.x), "=f"(v2.y) : "r"(base + arow0 + sa + 32u));
            asm volatile("ld.shared.v2.f32 {%0,%1},[%2];" : "=f"(v3.x), "=f"(v3.y) : "r"(base + arow1 + sa + 32u));

            uint32_t ahi[4], alo[4];
            {
                const float2 vv[4] = {v0, v1, v2, v3};
                #pragma unroll
                for (int i = 0; i < 4; i++) {
                    const __half2 h = __float22half2_rn(vv[i]);
                    const float2 f = __half22float2(h);
                    ahi[i] = h2u(h);
                    alo[i] = h2u(__floats2half2_rn(vv[i].x - f.x, vv[i].y - f.y));
                }
            }

            const uint32_t b0a = base + (uint32_t)A_BYTES
                               + (uint32_t)(((g * 2 + s) * 2) * 2048)
                               + (uint32_t)(gid * 32 + tid4 * 8);
            #pragma unroll
            for (int nt = 0; nt < 8; nt++) {
                uint32_t bh0, bh1, bl0, bl1;
                asm volatile("ld.shared.v2.b32 {%0,%1},[%2];"
                             : "=r"(bh0), "=r"(bh1) : "r"(b0a + (uint32_t)(nt * 256)));
                asm volatile("ld.shared.v2.b32 {%0,%1},[%2];"
                             : "=r"(bl0), "=r"(bl1) : "r"(b0a + (uint32_t)(nt * 256) + 2048u));
                MMAH(acc[nt], ahi[0], ahi[1], ahi[2], ahi[3], bh0, bh1);
                MMAH(acc[nt], ahi[0], ahi[1], ahi[2], ahi[3], bl0, bl1);
                MMAH(acc[nt], alo[0], alo[1], alo[2], alo[3], bh0, bh1);
            }
        }
        bufc = bufc + 1; if (bufc >= NSTAGE) bufc -= NSTAGE;
    }
    __syncthreads();

    // ---- split-K(2) reduction into logits smem [64][68] ----
    #pragma unroll
    for (int gg = 0; gg < 2; gg++) {
        if (g == gg) {
            const int r = tq * 16 + gid;
            #pragma unroll
            for (int nt = 0; nt < 8; nt++) {
                const int col = nt * 8 + tid4 * 2;
                if (gg == 0) {
                    smem[r * 68 + col]           = acc[nt][0];
                    smem[r * 68 + col + 1]       = acc[nt][1];
                    smem[(r + 8) * 68 + col]     = acc[nt][2];
                    smem[(r + 8) * 68 + col + 1] = acc[nt][3];
                } else {
                    smem[r * 68 + col]           += acc[nt][0];
                    smem[r * 68 + col + 1]       += acc[nt][1];
                    smem[(r + 8) * 68 + col]     += acc[nt][2];
                    smem[(r + 8) * 68 + col + 1] += acc[nt][3];
                }
            }
        }
        __syncthreads();
    }

    if (tid < MT) {
        const float* row = smem + tid * 68;
        float best1 = -3.4e38f, best2 = -3.4e38f;
        int i1 = 0, i2 = 0;
        #pragma unroll 8
        for (int e = 0; e < Edim; e++) {
            const float l = row[e];
            if (l > best1) { best2 = best1; i2 = i1; best1 = l; i1 = e; }
            else if (l > best2) { best2 = l; i2 = e; }
        }
        float Z = 0.0f;
        #pragma unroll 8
        for (int e = 0; e < Edim; e++) Z += expf(row[e] - best1);
        const float s1 = 1.0f / Z;
        const float s2 = expf(best2 - best1) / Z;
        const float p1 = 1.0f / (1.0f + expf(s2 - s1));
        const float p2 = 1.0f - p1;

        const int m = m0 + tid;
        out[2 * m + 0] = p1;
        out[2 * m + 1] = p2;
        float* oi = out + 2 * T;              // indices stored as float values
        oi[2 * m + 0] = (float)i1;
        oi[2 * m + 1] = (float)i2;
    }
    if (blockIdx.x == 0 && tid == 0) out[4 * T] = 0.0f;
}

extern "C" void kernel_launch(void* const* d_in, const int* in_sizes, int n_in,
                              void* d_out, int out_size)
{
    const float* x = (const float*)d_in[0];
    const float* W = (const float*)d_in[1];
    int T = in_sizes[0] / Hdim;   // 16384
    (void)n_in; (void)out_size;

    static bool attr_done = false;
    if (!attr_done) {
        cudaFuncSetAttribute(moe_gate_v10_kernel,
                             cudaFuncAttributeMaxDynamicSharedMemorySize, SMEM_BYTES);
        attr_done = true;
    }
    split_w_kernel<<<1024, 256>>>(W);
    moe_gate_v10_kernel<<<T / MT, 256, SMEM_BYTES>>>(x, (float*)d_out, T);
}